// round 2
// baseline (speedup 1.0000x reference)
#include <cuda_runtime.h>

// TripletCenterLoss — collapsed to an [B x NC] distance problem.
// B=8192, D=512, NC=55, margin=0.2
//
// dist_ap[i] = d(i, targets[i])
// dist_an[i] = min over present classes c != targets[i] of d(i, c)
// loss = mean(relu(ap - an + margin)), prec = mean(an > ap)
//
// NOTE: targets arrive as int32 (JAX x64 disabled downcasts int64).

#define BB 8192
#define DD 512
#define NC 55
#define MARGINF 0.2f

// ---- device scratch (no allocations allowed) ----
__device__ float  g_cn[56];       // ||center_c||^2, g_cn[55] = 0 (pad)
__device__ int    g_present[56];  // class appears in targets
__device__ float2 g_partial[128]; // per-block (loss_sum, prec_sum)

// ---- packed f32x2 helpers (sm_100+) ----
__device__ __forceinline__ void fma2(unsigned long long &d,
                                     unsigned long long a,
                                     unsigned long long b) {
    asm("fma.rn.f32x2 %0, %1, %2, %0;" : "+l"(d) : "l"(a), "l"(b));
}
__device__ __forceinline__ float lo32(unsigned long long v) {
    return __int_as_float((int)(unsigned)(v & 0xffffffffull));
}
__device__ __forceinline__ float hi32(unsigned long long v) {
    return __int_as_float((int)(unsigned)(v >> 32));
}

// ============================================================
// Kernel 1: class-present mask + center norms
// ============================================================
__global__ void prep_kernel(const int* __restrict__ tgt,
                            const float* __restrict__ cen) {
    __shared__ int flags[56];
    int tid = threadIdx.x;                 // 1024 threads
    if (tid < 56) flags[tid] = 0;
    __syncthreads();

    #pragma unroll 8
    for (int t = tid; t < BB; t += 1024) {
        int c = tgt[t];
        flags[c] = 1;                      // benign race, writes 1
    }
    __syncthreads();
    if (tid < 56) g_present[tid] = flags[tid];

    // center norms: one warp per class, classes strided by 32 warps
    int w = tid >> 5, lane = tid & 31;
    for (int c = w; c < NC; c += 32) {
        const float4* p = (const float4*)(cen + (size_t)c * DD);
        float s = 0.0f;
        #pragma unroll
        for (int e = 0; e < 4; e++) {
            float4 v = p[lane + 32 * e];
            s += v.x * v.x + v.y * v.y + v.z * v.z + v.w * v.w;
        }
        #pragma unroll
        for (int o = 16; o; o >>= 1) s += __shfl_xor_sync(0xffffffffu, s, o);
        if (lane == 0) g_cn[c] = s;
    }
    if (tid == 0) g_cn[55] = 0.0f;
}

// ============================================================
// Kernel 2: main — S = X @ C^T via packed f32x2 FMA, fused epilogue
// block: 128 threads = 16 M-threads x 8 N-threads
// thread tile: 4 rows x 7 classes; block tile: 64 rows x 56 classes
// grid: 128 blocks (8192 rows exactly)
// ============================================================
__global__ __launch_bounds__(128, 1)
void tcl_main_kernel(const float* __restrict__ x,
                     const int* __restrict__ tgt,
                     const float* __restrict__ cen) {
    const int tid = threadIdx.x;
    const int m = tid >> 3;        // 0..15
    const int n = tid & 7;         // 0..7
    const int r0 = blockIdx.x * 64 + m * 4;

    const ulonglong2* __restrict__ xr[4];
    #pragma unroll
    for (int i = 0; i < 4; i++)
        xr[i] = (const ulonglong2*)(x + (size_t)(r0 + i) * DD);

    int cls[7];
    const ulonglong2* __restrict__ cb[7];
    #pragma unroll
    for (int j = 0; j < 7; j++) {
        cls[j] = n * 7 + j;                       // 0..55 (55 = pad)
        int cc = cls[j] < NC ? cls[j] : NC - 1;   // clamp pad for loads
        cb[j] = (const ulonglong2*)(cen + (size_t)cc * DD);
    }

    unsigned long long acc[4][7];
    unsigned long long xn2[4];
    #pragma unroll
    for (int i = 0; i < 4; i++) {
        xn2[i] = 0ull;
        #pragma unroll
        for (int j = 0; j < 7; j++) acc[i][j] = 0ull;
    }

    // K loop: 128 steps of 4 floats (as 2x f32x2)
    #pragma unroll 2
    for (int k = 0; k < DD / 4; k++) {
        ulonglong2 b[7];
        #pragma unroll
        for (int j = 0; j < 7; j++) b[j] = __ldg(cb[j] + k);
        #pragma unroll
        for (int i = 0; i < 4; i++) {
            ulonglong2 a = __ldg(xr[i] + k);
            fma2(xn2[i], a.x, a.x);
            fma2(xn2[i], a.y, a.y);
            #pragma unroll
            for (int j = 0; j < 7; j++) {
                fma2(acc[i][j], a.x, b[j].x);
                fma2(acc[i][j], a.y, b[j].y);
            }
        }
    }

    // epilogue
    float cnv[7];
    int pres[7];
    #pragma unroll
    for (int j = 0; j < 7; j++) {
        if (cls[j] < NC) {
            cnv[j] = g_cn[cls[j]];
            pres[j] = g_present[cls[j]];
        } else {
            cnv[j] = 0.0f;
            pres[j] = 0;
        }
    }

    float lsum = 0.0f, psum = 0.0f;
    #pragma unroll
    for (int i = 0; i < 4; i++) {
        float xn = lo32(xn2[i]) + hi32(xn2[i]);
        int tg = tgt[r0 + i];
        float ap = -1e30f, an = 1e30f;
        #pragma unroll
        for (int j = 0; j < 7; j++) {
            if (!pres[j]) continue;
            float S = lo32(acc[i][j]) + hi32(acc[i][j]);
            float d2 = xn + cnv[j] - 2.0f * S;
            float d = sqrtf(fmaxf(d2, 1e-12f));
            if (cls[j] == tg) ap = d;
            else an = fminf(an, d);
        }
        // combine across the 8 N-threads of this row (contiguous 8-lane group)
        #pragma unroll
        for (int o = 1; o < 8; o <<= 1) {
            ap = fmaxf(ap, __shfl_xor_sync(0xffffffffu, ap, o));
            an = fminf(an, __shfl_xor_sync(0xffffffffu, an, o));
        }
        if (n == 0) {
            lsum += fmaxf(ap - an + MARGINF, 0.0f);
            psum += (an > ap) ? 1.0f : 0.0f;
        }
    }

    __shared__ float2 red[16];
    if (n == 0) red[m] = make_float2(lsum, psum);
    __syncthreads();
    if (tid == 0) {
        float a = 0.0f, b = 0.0f;
        #pragma unroll
        for (int q = 0; q < 16; q++) { a += red[q].x; b += red[q].y; }
        g_partial[blockIdx.x] = make_float2(a, b);
    }
}

// ============================================================
// Kernel 3: deterministic finalize
// ============================================================
__global__ void finalize_kernel(float* __restrict__ out) {
    __shared__ float2 s[128];
    int t = threadIdx.x;
    s[t] = g_partial[t];
    __syncthreads();
    #pragma unroll
    for (int o = 64; o; o >>= 1) {
        if (t < o) {
            s[t].x += s[t + o].x;
            s[t].y += s[t + o].y;
        }
        __syncthreads();
    }
    if (t == 0) {
        out[0] = s[0].x / (float)BB;  // loss
        out[1] = s[0].y / (float)BB;  // prec
    }
}

extern "C" void kernel_launch(void* const* d_in, const int* in_sizes, int n_in,
                              void* d_out, int out_size) {
    const float* x   = (const float*)d_in[0];
    const int*   tgt = (const int*)d_in[1];
    const float* cen = (const float*)d_in[2];
    float* out = (float*)d_out;

    prep_kernel<<<1, 1024>>>(tgt, cen);
    tcl_main_kernel<<<128, 128>>>(x, tgt, cen);
    finalize_kernel<<<1, 128>>>(out);
}